// round 9
// baseline (speedup 1.0000x reference)
#include <cuda_runtime.h>

// B=8, T=2048, V=1024.
// c = idx[b,t]; q_1..q_m = occurrences of c in [0..t]; Cv(r) = inclusive prefix
// histogram:
//   L_t[v] = w2*( m*Cv(t) - sum_j Cv(q_j-1) ) + a0*m*[v==c]
//            + a1*#{j : q_j+1 <= t, idx(q_j+1)==v},  out = softmax(L_t).
// Single persistent kernel: setup phases (checkpointed prefix hists every 32
// positions + CSR occurrence lists) separated by grid-wide barriers, then the
// R6 main body (one warp per t, packed 2xu16 SIMD gather, warp-private smem
// bins) driven by a dynamic work counter. Weights pre-scaled by log2(e) so the
// softmax uses exp2f (same function, fewer FMULs).

namespace {
constexpr int B = 8, T = 2048, V = 1024;
constexpr int NSEG = 64;                     // T/32 segments
constexpr unsigned NUNITS = 8192;            // work units: 2 t's each
}

__device__ __align__(16) unsigned short g_cp[B][NSEG][V];  // excl. prefix ckpt
__device__ __align__(16) unsigned short g_row[B][T];
__device__ __align__(16) unsigned short g_off[B][V];       // CSR offsets
__device__ __align__(16) unsigned short g_occ[B][T];       // CSR positions
__device__ unsigned g_bar[4];                // monotonic barrier counters
__device__ unsigned g_work;                  // work counter (reset in P0)

#define GRID_BAR(W)                                                     \
    do {                                                                \
        __syncthreads();                                                \
        if (tid == 0) {                                                 \
            __threadfence();                                            \
            atomicAdd(&g_bar[W], 1u);                                   \
            volatile unsigned* _p = &g_bar[W];                          \
            const unsigned _tgt = base[W] + G;                          \
            while (*_p < _tgt) __nanosleep(64);                         \
            __threadfence();                                            \
        }                                                               \
        __syncthreads();                                                \
    } while (0)

__global__ __launch_bounds__(128, 8) void k_all(const int* __restrict__ idx,
                                                const float* __restrict__ vw,
                                                float* __restrict__ out) {
    __shared__ float acc[4][V];              // warp-private bins (16 KB)
    __shared__ unsigned s_scan[4];
    const unsigned G = gridDim.x;
    const int bid = blockIdx.x;
    const int tid = threadIdx.x, lane = tid & 31, warp = tid >> 5;

    // Barrier bases: counters are monotonic across graph replays; at launch
    // start each counter is a multiple of G, and fewer than G arrivals of the
    // current launch can precede this read, so floor(c/G)*G is this launch's
    // base for every barrier.
    unsigned base[4];
    #pragma unroll
    for (int k = 0; k < 4; k++)
        base[k] = (((volatile unsigned*)g_bar)[k] / G) * G;

    // ---- P0: reset work counter; per-(b,seg): zero ckpt row + seg hist ----
    if (bid == 0 && tid == 0) g_work = 0u;
    if (bid < B * NSEG) {
        const int b = bid >> 6, seg = bid & 63;
        reinterpret_cast<uint4*>(&g_cp[b][seg][0])[tid] = make_uint4(0, 0, 0, 0);
        __syncthreads();                      // zero visible before hist stores
        if (tid < 32) {
            const unsigned tok = (unsigned)idx[b * T + seg * 32 + lane];
            g_row[b][seg * 32 + lane] = (unsigned short)tok;
            const unsigned mask = __match_any_sync(0xffffffffu, tok);
            if ((mask & ((1u << lane) - 1u)) == 0u)
                g_cp[b][seg][tok] = (unsigned short)__popc(mask);
        }
    }
    GRID_BAR(0);

    // ---- P1: per-(b,v) exclusive prefix over segments; totals -> g_off ----
    {
        const int th = bid * 128 + tid;
        if (th < B * V) {
            const int b = th >> 10, v = th & 1023;
            unsigned run = 0;
            #pragma unroll 8
            for (int k = 0; k < NSEG; k++) {
                const unsigned x = g_cp[b][k][v];
                g_cp[b][k][v] = (unsigned short)run;
                run += x;
            }
            g_off[b][v] = (unsigned short)run;   // temp: totals
        }
    }
    GRID_BAR(1);

    // ---- P2: per-b exclusive scan of totals -> CSR offsets ----
    if (bid < B) {
        const int b = bid;
        const int v0 = tid * 8;
        unsigned vals[8];
        #pragma unroll
        for (int k = 0; k < 8; k++) vals[k] = g_off[b][v0 + k];
        unsigned S = 0;
        #pragma unroll
        for (int k = 0; k < 8; k++) { const unsigned x = vals[k]; vals[k] = S; S += x; }
        unsigned incl = S;
        #pragma unroll
        for (int o = 1; o < 32; o <<= 1) {
            const unsigned n = __shfl_up_sync(0xffffffffu, incl, o);
            if (lane >= o) incl += n;
        }
        if (lane == 31) s_scan[warp] = incl;
        __syncthreads();
        unsigned wex = 0;
        #pragma unroll
        for (int w = 0; w < 4; w++)
            if (w < warp) wex += s_scan[w];
        const unsigned ex = wex + incl - S;
        #pragma unroll
        for (int k = 0; k < 8; k++)
            g_off[b][v0 + k] = (unsigned short)(ex + vals[k]);
    }
    GRID_BAR(2);

    // ---- P3: CSR fill (sorted by construction) ----
    if (bid < B * NSEG) {
        const int b = bid >> 6, seg = bid & 63;
        if (tid < 32) {
            const int s = seg * 32 + lane;
            const unsigned tok = g_row[b][s];
            const unsigned mask = __match_any_sync(0xffffffffu, tok);
            const int rank = __popc(mask & ((1u << lane) - 1u));
            const int slot = (int)g_off[b][tok] + (int)g_cp[b][seg][tok] + rank;
            g_occ[b][slot] = (unsigned short)s;
        }
    }
    GRID_BAR(3);

    // ---- P4: main — one warp per t, dynamic work units of 2 t's ----
    const float w0 = vw[0], w1 = vw[1], w2 = vw[2];
    const float L2E = 1.4426950408889634f;   // weights scaled: softmax via exp2
    const float w2s = w2 * L2E;
    const float a0s = (w0 - w2) * L2E, a1s = (w1 - w2) * L2E;
    float* const wacc = acc[warp];
    const int voff = lane * 4;               // lane owns v = k*128 + voff + 0..3

    #pragma unroll
    for (int k = 0; k < 8; k++)
        *reinterpret_cast<float4*>(&wacc[k * 128 + voff]) =
            make_float4(0.f, 0.f, 0.f, 0.f);
    __syncwarp();

    for (;;) {
        unsigned u;
        if (lane == 0) u = atomicAdd(&g_work, 1u);
        u = __shfl_sync(0xffffffffu, u, 0);
        if (u >= NUNITS) break;

        const int b = (int)(u >> 10);        // 1024 units per b
        const int t0 = (int)(u & 1023u) * 2;
        const int seg = t0 >> 5, seg0 = seg << 5;
        const unsigned stok = g_row[b][seg0 + lane];
        const unsigned short* const cprow_p = &g_cp[b][seg][0];
        const unsigned short* const cpzb = &g_cp[b][0][0];
        const unsigned short* const rowb = g_row[b];
        const unsigned short* const occb = g_occ[b];

        #pragma unroll 1
        for (int i = 0; i < 2; i++) {
            const int t = t0 + i;
            const int ti = t - seg0;         // 0..31
            const unsigned c = __shfl_sync(0xffffffffu, stok, ti);
            const unsigned ball = __ballot_sync(0xffffffffu, stok == c);
            const int m = (int)cprow_p[c] + __popc(ball & ((2u << ti) - 1u));
            const int offc = g_off[b][c];
            const float fm = (float)m;
            const bool fast = (m <= 31);     // m*CP <= 31*2048 < 2^16
            const unsigned mu = fast ? (unsigned)m : 0u;

            // packed 2xu16 SIMD: pa = m*CP[seg] - sum_j CP[(q_j-1)>>5]
            unsigned pa[16];
            #pragma unroll
            for (int k = 0; k < 8; k++) {
                const uint2 w =
                    *reinterpret_cast<const uint2*>(cprow_p + k * 128 + voff);
                pa[2 * k]     = mu * w.x;
                pa[2 * k + 1] = mu * w.y;
            }

            for (int jb = 0; jb < m; jb += 32) {
                const int nj = min(32, m - jb);
                unsigned qv = 0;
                if (lane < nj) qv = occb[offc + jb + lane];
                for (int j = 0; j < nj; j++) {
                    const int q = __shfl_sync(0xffffffffu, qv, j);
                    if (q > 0) {
                        const int qm1 = q - 1, qp = qm1 >> 5;
                        if (fast) {
                            const unsigned short* rowq = cpzb + qp * V;
                            #pragma unroll
                            for (int k = 0; k < 8; k++) {
                                const uint2 w = *reinterpret_cast<const uint2*>(
                                    rowq + k * 128 + voff);
                                pa[2 * k]     -= w.x;
                                pa[2 * k + 1] -= w.y;
                            }
                        }
                        // sub-checkpoint remainder of Cv(q-1)
                        const unsigned rtok = rowb[(qp << 5) + lane];
                        if (lane <= (qm1 & 31))
                            atomicAdd(&wacc[rtok], -w2s);
                    }
                    if (q < t && lane == 0)  // bigram c -> next token
                        atomicAdd(&wacc[rowb[q + 1]], a1s);
                }
            }

            if (!fast) {  // exact cold path for m > 31 (i32, overflow-safe)
                #pragma unroll 1
                for (int k = 0; k < 8; k++) {
                    const uint2 w =
                        *reinterpret_cast<const uint2*>(cprow_p + k * 128 + voff);
                    int l0 = m * (int)(w.x & 0xffffu);
                    int l1 = m * (int)(w.x >> 16);
                    int l2 = m * (int)(w.y & 0xffffu);
                    int l3 = m * (int)(w.y >> 16);
                    for (int j = 0; j < m; j++) {
                        const int q = occb[offc + j];
                        if (q > 0) {
                            const uint2 uu = *reinterpret_cast<const uint2*>(
                                cpzb + ((q - 1) >> 5) * V + k * 128 + voff);
                            l0 -= (int)(uu.x & 0xffffu); l1 -= (int)(uu.x >> 16);
                            l2 -= (int)(uu.y & 0xffffu); l3 -= (int)(uu.y >> 16);
                        }
                    }
                    atomicAdd(&wacc[k * 128 + voff + 0], w2s * (float)l0);
                    atomicAdd(&wacc[k * 128 + voff + 1], w2s * (float)l1);
                    atomicAdd(&wacc[k * 128 + voff + 2], w2s * (float)l2);
                    atomicAdd(&wacc[k * 128 + voff + 3], w2s * (float)l3);
                }
            }

            // remainder of Cv(t) over this segment + a0 term
            if (lane <= ti) atomicAdd(&wacc[stok], w2s * fm);
            if (lane == ti) atomicAdd(&wacc[c], a0s * fm);
            __syncwarp();

            // assemble log2-scaled logits, warp-local softmax via exp2
            float a[32];
            float vmax = -3.0e38f;
            #pragma unroll
            for (int k = 0; k < 8; k++) {
                const float4 av =
                    *reinterpret_cast<const float4*>(&wacc[k * 128 + voff]);
                *reinterpret_cast<float4*>(&wacc[k * 128 + voff]) =
                    make_float4(0.f, 0.f, 0.f, 0.f);  // re-zero for next t
                a[4 * k + 0] = fmaf(w2s, (float)(pa[2 * k] & 0xffffu),     av.x);
                a[4 * k + 1] = fmaf(w2s, (float)(pa[2 * k] >> 16),         av.y);
                a[4 * k + 2] = fmaf(w2s, (float)(pa[2 * k + 1] & 0xffffu), av.z);
                a[4 * k + 3] = fmaf(w2s, (float)(pa[2 * k + 1] >> 16),     av.w);
                vmax = fmaxf(vmax, fmaxf(fmaxf(a[4 * k], a[4 * k + 1]),
                                         fmaxf(a[4 * k + 2], a[4 * k + 3])));
            }
            #pragma unroll
            for (int o = 16; o; o >>= 1)
                vmax = fmaxf(vmax, __shfl_xor_sync(0xffffffffu, vmax, o));

            float ssum = 0.f;
            #pragma unroll
            for (int k = 0; k < 32; k++) {
                a[k] = exp2f(a[k] - vmax);
                ssum += a[k];
            }
            #pragma unroll
            for (int o = 16; o; o >>= 1)
                ssum += __shfl_xor_sync(0xffffffffu, ssum, o);
            const float inv = 1.0f / ssum;

            float* const orow = out + (size_t)(b * T + t) * V + voff;
            #pragma unroll
            for (int k = 0; k < 8; k++)
                *reinterpret_cast<float4*>(orow + k * 128) =
                    make_float4(a[4 * k] * inv, a[4 * k + 1] * inv,
                                a[4 * k + 2] * inv, a[4 * k + 3] * inv);

            __syncwarp();   // acc re-zero visible before next t's atomics
        }
    }
}

extern "C" void kernel_launch(void* const* d_in, const int* in_sizes, int n_in,
                              void* d_out, int out_size) {
    const int*   idx = (const int*)d_in[0];
    const float* vw  = (const float*)d_in[1];
    float*       out = (float*)d_out;
    (void)in_sizes; (void)n_in; (void)out_size;

    int dev = 0, sm = 148;
    cudaGetDevice(&dev);
    cudaDeviceGetAttribute(&sm, cudaDevAttrMultiProcessorCount, dev);
    const int G = sm * 8;    // exactly co-resident: 64 regs, 16.1 KB smem

    k_all<<<G, 128>>>(idx, vw, out);
}

// round 10
// speedup vs baseline: 1.3544x; 1.3544x over previous
#include <cuda_runtime.h>

// B=8, T=2048, V=1024.
// c = idx[b,t]; q_1..q_m = occurrences of c in [0..t]; C_v(r) = inclusive
// prefix histogram:
//   L_t[v] = w2*( m*C_v(t) - sum_j C_v(q_j-1) ) + a0*m*[v==c]
//            + a1*#{j : q_j+1 <= t, idx(q_j+1)==v},   out = softmax(L_t).
// Full per-position prefix rows g_pp (u16, 32MB, L2-resident) eliminate all
// sub-checkpoint remainder scatters. Main: one warp per t, packed 2xu16 SIMD,
// corrections = m+1 single-lane smem atomics, softmax via ex2.approx.

namespace {
constexpr int B = 8, T = 2048, V = 1024;
constexpr int NSEG = 64;                    // T/32 segments
constexpr int TPW = 2;                      // t's per warp
constexpr int TPB = 4 * TPW;                // t's per block
}

__device__ __align__(16) unsigned short g_cp[B][NSEG][V];  // excl. seg ckpt
__device__ __align__(16) unsigned short g_pp[B][T][V];     // incl. full prefix
__device__ __align__(16) unsigned short g_row[B][T];
__device__ __align__(16) unsigned short g_off[B][V];       // CSR offsets
__device__ __align__(16) unsigned short g_occ[B][T];       // CSR positions
__device__ __align__(16) unsigned short g_zero[V];         // stays all-zero

__device__ __forceinline__ float ex2(float x) {
    float y;
    asm("ex2.approx.ftz.f32 %0, %1;" : "=f"(y) : "f"(x));
    return y;
}

// ---- K1: zero + seg hist + prefix + offsets + CSR fill (1 block per b) ----
__global__ __launch_bounds__(1024) void k_setup(const int* __restrict__ idx) {
    __shared__ unsigned short srow[T];
    __shared__ unsigned wsum[32];
    const int b = blockIdx.x;
    const int tid = threadIdx.x, lane = tid & 31, warp = tid >> 5;

    const int2 tt = reinterpret_cast<const int2*>(idx + b * T)[tid];
    srow[2 * tid]     = (unsigned short)tt.x;
    srow[2 * tid + 1] = (unsigned short)tt.y;
    reinterpret_cast<ushort2*>(g_row[b])[tid] =
        make_ushort2((unsigned short)tt.x, (unsigned short)tt.y);
    const uint4 z = make_uint4(0, 0, 0, 0);
    #pragma unroll
    for (int k = 0; k < 8; k++)
        reinterpret_cast<uint4*>(&g_cp[b][0][0])[k * 1024 + tid] = z;
    __syncthreads();

    #pragma unroll
    for (int sg = warp; sg < NSEG; sg += 32) {
        const unsigned tok = srow[sg * 32 + lane];
        const unsigned mask = __match_any_sync(0xffffffffu, tok);
        if ((mask & ((1u << lane) - 1u)) == 0u)
            g_cp[b][sg][tok] = (unsigned short)__popc(mask);
    }
    __syncthreads();

    unsigned run = 0;
    #pragma unroll 8
    for (int k = 0; k < NSEG; k++) {
        const unsigned x = g_cp[b][k][tid];
        g_cp[b][k][tid] = (unsigned short)run;
        run += x;
    }

    const unsigned total = run;
    unsigned incl = total;
    #pragma unroll
    for (int o = 1; o < 32; o <<= 1) {
        const unsigned n = __shfl_up_sync(0xffffffffu, incl, o);
        if (lane >= o) incl += n;
    }
    if (lane == 31) wsum[warp] = incl;
    __syncthreads();
    unsigned wex = 0;
    #pragma unroll
    for (int w = 0; w < 32; w++)
        if (w < warp) wex += wsum[w];
    g_off[b][tid] = (unsigned short)(wex + incl - total);
    __syncthreads();

    #pragma unroll
    for (int sg = warp; sg < NSEG; sg += 32) {
        const int s = sg * 32 + lane;
        const unsigned tok = srow[s];
        const unsigned mask = __match_any_sync(0xffffffffu, tok);
        const int rank = __popc(mask & ((1u << lane) - 1u));
        const int slot = (int)g_off[b][tok] + (int)g_cp[b][sg][tok] + rank;
        g_occ[b][slot] = (unsigned short)s;
    }
}

// ---- K2: expand checkpoints to full per-position prefix rows ----
// One block per (seg, b); thread owns 4 consecutive v's, walks the segment's
// 32 positions keeping packed running counts; one STG.64 per row. Barrier-free
// after the token stage.
__global__ __launch_bounds__(256) void k_expand() {
    __shared__ unsigned short stok[32];
    const int seg = blockIdx.x, b = blockIdx.y;
    const int tid = threadIdx.x;
    if (tid < 32) stok[tid] = g_row[b][seg * 32 + tid];
    const int v0 = tid * 4;
    const uint2 cp = *reinterpret_cast<const uint2*>(&g_cp[b][seg][v0]);
    __syncthreads();

    unsigned a = cp.x, c = cp.y;            // packed (v0,v1), (v2,v3)
    #pragma unroll
    for (int s = 0; s < 32; s++) {
        const unsigned tok = stok[s];
        if (tok == (unsigned)(v0 + 0)) a += 1u;
        if (tok == (unsigned)(v0 + 1)) a += 0x10000u;
        if (tok == (unsigned)(v0 + 2)) c += 1u;
        if (tok == (unsigned)(v0 + 3)) c += 0x10000u;
        *reinterpret_cast<uint2*>(&g_pp[b][seg * 32 + s][v0]) =
            make_uint2(a, c);
    }
}

// ---- K3: main — one warp per t; 4 warps x TPW t's; no block barriers ----
__global__ __launch_bounds__(128, 8) void k4_main(const float* __restrict__ vw,
                                                  float* __restrict__ out) {
    __shared__ float acc[4][V];             // warp-private correction bins
    const int b = blockIdx.y;
    const int t_base = blockIdx.x * TPB;
    const int tid = threadIdx.x, lane = tid & 31, warp = tid >> 5;
    float* const wacc = acc[warp];
    const int voff = lane * 4;              // lane owns v = k*128 + voff + 0..3

    #pragma unroll
    for (int k = 0; k < 8; k++)
        *reinterpret_cast<float4*>(&wacc[k * 128 + voff]) =
            make_float4(0.f, 0.f, 0.f, 0.f);

    const float w0 = vw[0], w1 = vw[1], w2 = vw[2];
    const float L2E = 1.4426950408889634f;  // softmax in log2 domain
    const float w2s = w2 * L2E;
    const float a0s = (w0 - w2) * L2E, a1s = (w1 - w2) * L2E;
    const unsigned short* const rowb = g_row[b];
    const unsigned short* const offb = g_off[b];
    const unsigned short* const occb = g_occ[b];
    const unsigned short* const ppb  = &g_pp[b][0][0];
    __syncwarp();

    for (int i = 0; i < TPW; i++) {
        const int t = t_base + warp * TPW + i;
        const unsigned c = rowb[t];
        const int m = (int)g_pp[b][t][c];   // inclusive count of c at t (>=1)
        const int offc = offb[c];
        const bool fast = (m <= 31);        // m*C <= 31*2048 < 2^16
        const unsigned mu = fast ? (unsigned)m : 0u;
        const unsigned short* const rt = ppb + (size_t)t * V;

        // packed 2xu16 SIMD: pa = m*C(t) - sum_j C(q_j-1)  (borrow-free)
        unsigned pa[16];
        #pragma unroll
        for (int k = 0; k < 8; k++) {
            const uint2 w = *reinterpret_cast<const uint2*>(rt + k * 128 + voff);
            pa[2 * k]     = mu * w.x;
            pa[2 * k + 1] = mu * w.y;
        }

        for (int jb = 0; jb < m; jb += 32) {
            const int nj = min(32, m - jb);
            unsigned qv = 0;
            if (lane < nj) qv = occb[offc + jb + lane];
            for (int j = 0; j < nj; j++) {
                const int q = __shfl_sync(0xffffffffu, qv, j);
                if (fast) {
                    const unsigned short* rq =
                        (q > 0) ? ppb + (size_t)(q - 1) * V : g_zero;
                    #pragma unroll
                    for (int k = 0; k < 8; k++) {
                        const uint2 u =
                            *reinterpret_cast<const uint2*>(rq + k * 128 + voff);
                        pa[2 * k]     -= u.x;
                        pa[2 * k + 1] -= u.y;
                    }
                }
                if (q < t && lane == 0)     // bigram c -> next token
                    atomicAdd(&wacc[rowb[q + 1]], a1s);
            }
        }

        if (!fast) {  // exact cold path for m > 31 (i32, overflow-safe)
            #pragma unroll 1
            for (int k = 0; k < 8; k++) {
                const uint2 w =
                    *reinterpret_cast<const uint2*>(rt + k * 128 + voff);
                int l0 = m * (int)(w.x & 0xffffu);
                int l1 = m * (int)(w.x >> 16);
                int l2 = m * (int)(w.y & 0xffffu);
                int l3 = m * (int)(w.y >> 16);
                for (int j = 0; j < m; j++) {
                    const int q = occb[offc + j];
                    if (q > 0) {
                        const uint2 u = *reinterpret_cast<const uint2*>(
                            ppb + (size_t)(q - 1) * V + k * 128 + voff);
                        l0 -= (int)(u.x & 0xffffu); l1 -= (int)(u.x >> 16);
                        l2 -= (int)(u.y & 0xffffu); l3 -= (int)(u.y >> 16);
                    }
                }
                atomicAdd(&wacc[k * 128 + voff + 0], w2s * (float)l0);
                atomicAdd(&wacc[k * 128 + voff + 1], w2s * (float)l1);
                atomicAdd(&wacc[k * 128 + voff + 2], w2s * (float)l2);
                atomicAdd(&wacc[k * 128 + voff + 3], w2s * (float)l3);
            }
        }

        if (lane == 0) atomicAdd(&wacc[c], a0s * (float)m);   // a0 term
        __syncwarp();

        // assemble log2-scaled logits, warp-local softmax via EX2
        float a[32];
        float vmax = -3.0e38f;
        #pragma unroll
        for (int k = 0; k < 8; k++) {
            const float4 av =
                *reinterpret_cast<const float4*>(&wacc[k * 128 + voff]);
            *reinterpret_cast<float4*>(&wacc[k * 128 + voff]) =
                make_float4(0.f, 0.f, 0.f, 0.f);  // re-zero for next t
            a[4 * k + 0] = fmaf(w2s, (float)(pa[2 * k] & 0xffffu),     av.x);
            a[4 * k + 1] = fmaf(w2s, (float)(pa[2 * k] >> 16),         av.y);
            a[4 * k + 2] = fmaf(w2s, (float)(pa[2 * k + 1] & 0xffffu), av.z);
            a[4 * k + 3] = fmaf(w2s, (float)(pa[2 * k + 1] >> 16),     av.w);
            vmax = fmaxf(vmax, fmaxf(fmaxf(a[4 * k], a[4 * k + 1]),
                                     fmaxf(a[4 * k + 2], a[4 * k + 3])));
        }
        #pragma unroll
        for (int o = 16; o; o >>= 1)
            vmax = fmaxf(vmax, __shfl_xor_sync(0xffffffffu, vmax, o));

        float ssum = 0.f;
        #pragma unroll
        for (int k = 0; k < 32; k++) {
            a[k] = ex2(a[k] - vmax);
            ssum += a[k];
        }
        #pragma unroll
        for (int o = 16; o; o >>= 1)
            ssum += __shfl_xor_sync(0xffffffffu, ssum, o);
        const float inv = 1.0f / ssum;

        float* const orow = out + (size_t)(b * T + t) * V + voff;
        #pragma unroll
        for (int k = 0; k < 8; k++)
            *reinterpret_cast<float4*>(orow + k * 128) =
                make_float4(a[4 * k] * inv, a[4 * k + 1] * inv,
                            a[4 * k + 2] * inv, a[4 * k + 3] * inv);

        __syncwarp();   // acc re-zero visible before next t's atomics
    }
}

extern "C" void kernel_launch(void* const* d_in, const int* in_sizes, int n_in,
                              void* d_out, int out_size) {
    const int*   idx = (const int*)d_in[0];
    const float* vw  = (const float*)d_in[1];
    float*       out = (float*)d_out;
    (void)in_sizes; (void)n_in; (void)out_size;

    k_setup <<<dim3(B), 1024>>>(idx);
    k_expand<<<dim3(NSEG, B), 256>>>();
    k4_main <<<dim3(T / TPB, B), 128>>>(vw, out);
}

// round 11
// speedup vs baseline: 1.3754x; 1.0155x over previous
#include <cuda_runtime.h>

// B=8, T=2048, V=1024.
// c = idx[b,t]; q_1..q_m = occurrences of c in [0..t]; C_v(r) = inclusive
// prefix histogram:
//   L_t[v] = w2*( m*C_v(t) - sum_j C_v(q_j-1) ) + a0*m*[v==c]
//            + a1*#{j : q_j+1 <= t, idx(q_j+1)==v},   out = softmax(L_t).
// Setup builds exclusive segment checkpoints (every 32 pos) + CSR occurrence
// lists entirely in 128KB shared memory (one block per b), then k_expand
// materializes full per-position prefix rows g_pp (u16, 32MB, L2-resident).
// Main: one warp per t, packed 2xu16 SIMD gather over g_pp rows, m+1
// single-lane smem atomics, softmax via ex2.approx in log2 domain.

namespace {
constexpr int B = 8, T = 2048, V = 1024;
constexpr int NSEG = 64;                    // T/32 segments
constexpr int TPW = 2;                      // t's per warp
constexpr int TPB = 4 * TPW;                // t's per block
constexpr int SETUP_SMEM = NSEG * V * 2 + T * 2 + V * 2 + 128 * 4;
}

__device__ __align__(16) unsigned short g_cp[B][NSEG][V];  // excl. seg ckpt
__device__ __align__(16) unsigned short g_pp[B][T][V];     // incl. full prefix
__device__ __align__(16) unsigned short g_row[B][T];
__device__ __align__(16) unsigned short g_off[B][V];       // CSR offsets
__device__ __align__(16) unsigned short g_occ[B][T];       // CSR positions
__device__ __align__(16) unsigned short g_zero[V];         // stays all-zero

__device__ __forceinline__ float ex2(float x) {
    float y;
    asm("ex2.approx.ftz.f32 %0, %1;" : "=f"(y) : "f"(x));
    return y;
}

// ---- K1: full setup in shared memory (one block per b, 1024 threads) ----
__global__ __launch_bounds__(1024) void k_setup(const int* __restrict__ idx) {
    extern __shared__ __align__(16) unsigned char smem_raw[];
    unsigned short* const scp  = (unsigned short*)smem_raw;          // [64][1024]
    unsigned short* const srow = scp + NSEG * V;                     // [2048]
    unsigned short* const soff = srow + T;                           // [1024]
    unsigned* const wsum = (unsigned*)(soff + V);                    // [32]

    const int b = blockIdx.x;
    const int tid = threadIdx.x, lane = tid & 31, warp = tid >> 5;

    // row load (2 tokens/thread) + mirror to global
    const int2 tt = reinterpret_cast<const int2*>(idx + b * T)[tid];
    srow[2 * tid]     = (unsigned short)tt.x;
    srow[2 * tid + 1] = (unsigned short)tt.y;
    reinterpret_cast<ushort2*>(g_row[b])[tid] =
        make_ushort2((unsigned short)tt.x, (unsigned short)tt.y);

    // zero the 128KB count table
    const uint4 z = make_uint4(0, 0, 0, 0);
    #pragma unroll
    for (int k = 0; k < 8; k++)
        reinterpret_cast<uint4*>(scp)[k * 1024 + tid] = z;
    __syncthreads();

    // per-segment counts via match_any (warp w: segments w and w+32)
    #pragma unroll
    for (int sg = warp; sg < NSEG; sg += 32) {
        const unsigned tok = srow[sg * 32 + lane];
        const unsigned mask = __match_any_sync(0xffffffffu, tok);
        if ((mask & ((1u << lane) - 1u)) == 0u)
            scp[sg * V + tok] = (unsigned short)__popc(mask);
    }
    __syncthreads();

    // serial exclusive prefix over segments (v = tid), all in smem;
    // stream exclusive values to g_cp coalesced as we go
    unsigned run = 0;
    #pragma unroll 8
    for (int k = 0; k < NSEG; k++) {
        const unsigned x = scp[k * V + tid];
        scp[k * V + tid] = (unsigned short)run;
        g_cp[b][k][tid]  = (unsigned short)run;
        run += x;
    }

    // block exclusive scan of per-v totals -> CSR offsets
    const unsigned total = run;
    unsigned incl = total;
    #pragma unroll
    for (int o = 1; o < 32; o <<= 1) {
        const unsigned n = __shfl_up_sync(0xffffffffu, incl, o);
        if (lane >= o) incl += n;
    }
    if (lane == 31) wsum[warp] = incl;
    __syncthreads();
    unsigned wex = 0;
    #pragma unroll
    for (int w = 0; w < 32; w++)
        if (w < warp) wex += wsum[w];
    const unsigned short off = (unsigned short)(wex + incl - total);
    soff[tid] = off;
    g_off[b][tid] = off;
    __syncthreads();

    // CSR fill (sorted by construction), all reads from smem
    #pragma unroll
    for (int sg = warp; sg < NSEG; sg += 32) {
        const int s = sg * 32 + lane;
        const unsigned tok = srow[s];
        const unsigned mask = __match_any_sync(0xffffffffu, tok);
        const int rank = __popc(mask & ((1u << lane) - 1u));
        const int slot = (int)soff[tok] + (int)scp[sg * V + tok] + rank;
        g_occ[b][slot] = (unsigned short)s;
    }
}

// ---- K2: expand checkpoints to full per-position prefix rows ----
__global__ __launch_bounds__(256) void k_expand() {
    __shared__ unsigned short stok[32];
    const int seg = blockIdx.x, b = blockIdx.y;
    const int tid = threadIdx.x;
    if (tid < 32) stok[tid] = g_row[b][seg * 32 + tid];
    const int v0 = tid * 4;
    const uint2 cp = *reinterpret_cast<const uint2*>(&g_cp[b][seg][v0]);
    __syncthreads();

    unsigned a = cp.x, c = cp.y;            // packed (v0,v1), (v2,v3)
    #pragma unroll
    for (int s = 0; s < 32; s++) {
        const unsigned tok = stok[s];
        if (tok == (unsigned)(v0 + 0)) a += 1u;
        if (tok == (unsigned)(v0 + 1)) a += 0x10000u;
        if (tok == (unsigned)(v0 + 2)) c += 1u;
        if (tok == (unsigned)(v0 + 3)) c += 0x10000u;
        *reinterpret_cast<uint2*>(&g_pp[b][seg * 32 + s][v0]) =
            make_uint2(a, c);
    }
}

// ---- K3: main — one warp per t; 4 warps x TPW t's; no block barriers ----
__global__ __launch_bounds__(128, 8) void k4_main(const float* __restrict__ vw,
                                                  float* __restrict__ out) {
    __shared__ float acc[4][V];             // warp-private correction bins
    const int b = blockIdx.y;
    const int t_base = blockIdx.x * TPB;
    const int tid = threadIdx.x, lane = tid & 31, warp = tid >> 5;
    float* const wacc = acc[warp];
    const int voff = lane * 4;              // lane owns v = k*128 + voff + 0..3

    #pragma unroll
    for (int k = 0; k < 8; k++)
        *reinterpret_cast<float4*>(&wacc[k * 128 + voff]) =
            make_float4(0.f, 0.f, 0.f, 0.f);

    const float w0 = vw[0], w1 = vw[1], w2 = vw[2];
    const float L2E = 1.4426950408889634f;  // softmax in log2 domain
    const float w2s = w2 * L2E;
    const float a0s = (w0 - w2) * L2E, a1s = (w1 - w2) * L2E;
    const unsigned short* const rowb = g_row[b];
    const unsigned short* const offb = g_off[b];
    const unsigned short* const occb = g_occ[b];
    const unsigned short* const ppb  = &g_pp[b][0][0];
    __syncwarp();

    for (int i = 0; i < TPW; i++) {
        const int t = t_base + warp * TPW + i;
        const unsigned c = rowb[t];
        const int m = (int)g_pp[b][t][c];   // inclusive count of c at t (>=1)
        const int offc = offb[c];
        const bool fast = (m <= 31);        // m*C <= 31*2048 < 2^16
        const unsigned mu = fast ? (unsigned)m : 0u;
        const unsigned short* const rt = ppb + (size_t)t * V;

        // packed 2xu16 SIMD: pa = m*C(t) - sum_j C(q_j-1)  (borrow-free)
        unsigned pa[16];
        #pragma unroll
        for (int k = 0; k < 8; k++) {
            const uint2 w = *reinterpret_cast<const uint2*>(rt + k * 128 + voff);
            pa[2 * k]     = mu * w.x;
            pa[2 * k + 1] = mu * w.y;
        }

        for (int jb = 0; jb < m; jb += 32) {
            const int nj = min(32, m - jb);
            unsigned qv = 0;
            if (lane < nj) qv = occb[offc + jb + lane];
            for (int j = 0; j < nj; j++) {
                const int q = __shfl_sync(0xffffffffu, qv, j);
                if (fast) {
                    const unsigned short* rq =
                        (q > 0) ? ppb + (size_t)(q - 1) * V : g_zero;
                    #pragma unroll
                    for (int k = 0; k < 8; k++) {
                        const uint2 u =
                            *reinterpret_cast<const uint2*>(rq + k * 128 + voff);
                        pa[2 * k]     -= u.x;
                        pa[2 * k + 1] -= u.y;
                    }
                }
                if (q < t && lane == 0)     // bigram c -> next token
                    atomicAdd(&wacc[rowb[q + 1]], a1s);
            }
        }

        if (!fast) {  // exact cold path for m > 31 (i32, overflow-safe)
            #pragma unroll 1
            for (int k = 0; k < 8; k++) {
                const uint2 w =
                    *reinterpret_cast<const uint2*>(rt + k * 128 + voff);
                int l0 = m * (int)(w.x & 0xffffu);
                int l1 = m * (int)(w.x >> 16);
                int l2 = m * (int)(w.y & 0xffffu);
                int l3 = m * (int)(w.y >> 16);
                for (int j = 0; j < m; j++) {
                    const int q = occb[offc + j];
                    if (q > 0) {
                        const uint2 u = *reinterpret_cast<const uint2*>(
                            ppb + (size_t)(q - 1) * V + k * 128 + voff);
                        l0 -= (int)(u.x & 0xffffu); l1 -= (int)(u.x >> 16);
                        l2 -= (int)(u.y & 0xffffu); l3 -= (int)(u.y >> 16);
                    }
                }
                atomicAdd(&wacc[k * 128 + voff + 0], w2s * (float)l0);
                atomicAdd(&wacc[k * 128 + voff + 1], w2s * (float)l1);
                atomicAdd(&wacc[k * 128 + voff + 2], w2s * (float)l2);
                atomicAdd(&wacc[k * 128 + voff + 3], w2s * (float)l3);
            }
        }

        if (lane == 0) atomicAdd(&wacc[c], a0s * (float)m);   // a0 term
        __syncwarp();

        // assemble log2-scaled logits, warp-local softmax via EX2
        float a[32];
        float vmax = -3.0e38f;
        #pragma unroll
        for (int k = 0; k < 8; k++) {
            const float4 av =
                *reinterpret_cast<const float4*>(&wacc[k * 128 + voff]);
            *reinterpret_cast<float4*>(&wacc[k * 128 + voff]) =
                make_float4(0.f, 0.f, 0.f, 0.f);  // re-zero for next t
            a[4 * k + 0] = fmaf(w2s, (float)(pa[2 * k] & 0xffffu),     av.x);
            a[4 * k + 1] = fmaf(w2s, (float)(pa[2 * k] >> 16),         av.y);
            a[4 * k + 2] = fmaf(w2s, (float)(pa[2 * k + 1] & 0xffffu), av.z);
            a[4 * k + 3] = fmaf(w2s, (float)(pa[2 * k + 1] >> 16),     av.w);
            vmax = fmaxf(vmax, fmaxf(fmaxf(a[4 * k], a[4 * k + 1]),
                                     fmaxf(a[4 * k + 2], a[4 * k + 3])));
        }
        #pragma unroll
        for (int o = 16; o; o >>= 1)
            vmax = fmaxf(vmax, __shfl_xor_sync(0xffffffffu, vmax, o));

        float ssum = 0.f;
        #pragma unroll
        for (int k = 0; k < 32; k++) {
            a[k] = ex2(a[k] - vmax);
            ssum += a[k];
        }
        #pragma unroll
        for (int o = 16; o; o >>= 1)
            ssum += __shfl_xor_sync(0xffffffffu, ssum, o);
        const float inv = 1.0f / ssum;

        float* const orow = out + (size_t)(b * T + t) * V + voff;
        #pragma unroll
        for (int k = 0; k < 8; k++)
            *reinterpret_cast<float4*>(orow + k * 128) =
                make_float4(a[4 * k] * inv, a[4 * k + 1] * inv,
                            a[4 * k + 2] * inv, a[4 * k + 3] * inv);

        __syncwarp();   // acc re-zero visible before next t's atomics
    }
}

extern "C" void kernel_launch(void* const* d_in, const int* in_sizes, int n_in,
                              void* d_out, int out_size) {
    const int*   idx = (const int*)d_in[0];
    const float* vw  = (const float*)d_in[1];
    float*       out = (float*)d_out;
    (void)in_sizes; (void)n_in; (void)out_size;

    static bool attr_done = false;
    if (!attr_done) {
        cudaFuncSetAttribute(k_setup,
                             cudaFuncAttributeMaxDynamicSharedMemorySize,
                             SETUP_SMEM);
        attr_done = true;
    }

    k_setup <<<dim3(B), 1024, SETUP_SMEM>>>(idx);
    k_expand<<<dim3(NSEG, B), 256>>>();
    k4_main <<<dim3(T / TPB, B), 128>>>(vw, out);
}

// round 12
// speedup vs baseline: 1.3856x; 1.0074x over previous
#include <cuda_runtime.h>

// B=8, T=2048, V=1024.
// c = idx[b,t]; q_1..q_m = occurrences of c in [0..t]; C_v(r) = inclusive
// prefix histogram:
//   L_t[v] = w2*( m*C_v(t) - sum_j C_v(q_j-1) ) + a0*m*[v==c]
//            + a1*#{j : q_j+1 <= t, idx(q_j+1)==v},   out = softmax(L_t).
// Setup (one block per b, smem-resident): segment hists -> hierarchical
// PACKED u16 prefix scan (uint4 = 8 v-lanes per thread, 8x fewer LSU ops)
// -> CSR offsets -> CSR occurrence lists. k_expand materializes full
// per-position prefix rows g_pp (u16, 32MB, L2-resident). Main: one warp per
// t, packed 2xu16 SIMD gather over g_pp rows, m+1 single-lane smem atomics,
// softmax via ex2.approx in log2 domain.

namespace {
constexpr int B = 8, T = 2048, V = 1024;
constexpr int NSEG = 64;                    // T/32 segments
constexpr int TPW = 2;                      // t's per warp
constexpr int TPB = 4 * TPW;                // t's per block
constexpr int SETUP_SMEM =
    NSEG * V * 2      // scp  [64][1024] u16
    + T * 2           // srow [2048] u16
    + V * 2           // soff [1024] u16
    + 8 * V * 2       // stot [8][1024] u16
    + 16;             // wsum [4] u32
}

__device__ __align__(16) unsigned short g_cp[B][NSEG][V];  // excl. seg ckpt
__device__ __align__(16) unsigned short g_pp[B][T][V];     // incl. full prefix
__device__ __align__(16) unsigned short g_row[B][T];
__device__ __align__(16) unsigned short g_off[B][V];       // CSR offsets
__device__ __align__(16) unsigned short g_occ[B][T];       // CSR positions
__device__ __align__(16) unsigned short g_zero[V];         // stays all-zero

__device__ __forceinline__ float ex2(float x) {
    float y;
    asm("ex2.approx.ftz.f32 %0, %1;" : "=f"(y) : "f"(x));
    return y;
}
__device__ __forceinline__ uint4 add4(uint4 a, uint4 b) {
    return make_uint4(a.x + b.x, a.y + b.y, a.z + b.z, a.w + b.w);
}

// ---- K1: full setup in shared memory (one block per b, 1024 threads) ----
__global__ __launch_bounds__(1024) void k_setup(const int* __restrict__ idx) {
    extern __shared__ __align__(16) unsigned char smem_raw[];
    unsigned short* const scp  = (unsigned short*)smem_raw;      // [64][1024]
    unsigned short* const srow = scp + NSEG * V;                 // [2048]
    unsigned short* const soff = srow + T;                       // [1024]
    unsigned short* const stot = soff + V;                       // [8][1024]
    unsigned* const wsum = (unsigned*)(stot + 8 * V);            // [4]
    uint4* const scp4  = (uint4*)scp;
    uint4* const stot4 = (uint4*)stot;

    const int b = blockIdx.x;
    const int tid = threadIdx.x, lane = tid & 31;
    const int warp = tid >> 5;
    const int g = tid >> 7, vt = tid & 127;  // group 0..7, v-lane 0..127

    // row load (2 tokens/thread) + mirror to global; zero the count table
    const int2 tt = reinterpret_cast<const int2*>(idx + b * T)[tid];
    srow[2 * tid]     = (unsigned short)tt.x;
    srow[2 * tid + 1] = (unsigned short)tt.y;
    reinterpret_cast<ushort2*>(g_row[b])[tid] =
        make_ushort2((unsigned short)tt.x, (unsigned short)tt.y);
    const uint4 z = make_uint4(0, 0, 0, 0);
    #pragma unroll
    for (int k = 0; k < 8; k++)
        scp4[k * 1024 + tid] = z;
    __syncthreads();

    // per-segment counts via match_any (warp w: segments w and w+32)
    #pragma unroll
    for (int sg = warp; sg < NSEG; sg += 32) {
        const unsigned tok = srow[sg * 32 + lane];
        const unsigned mask = __match_any_sync(0xffffffffu, tok);
        if ((mask & ((1u << lane) - 1u)) == 0u)
            scp[sg * V + tok] = (unsigned short)__popc(mask);
    }
    __syncthreads();

    // 3a: group totals (thread owns 8 v's = one uint4 of packed u16 lanes)
    uint4 gsum = z;
    #pragma unroll
    for (int k = 0; k < 8; k++)
        gsum = add4(gsum, scp4[(g * 8 + k) * 128 + vt]);
    stot4[g * 128 + vt] = gsum;
    __syncthreads();

    // 3b: exclusive base over earlier groups
    uint4 base = z;
    for (int gg = 0; gg < g; gg++)
        base = add4(base, stot4[gg * 128 + vt]);

    // 3c: within-group exclusive scan; write final excl. prefix to smem+gmem
    uint4* const gcp4 = reinterpret_cast<uint4*>(&g_cp[b][0][0]);
    #pragma unroll
    for (int k = 0; k < 8; k++) {
        const int i4 = (g * 8 + k) * 128 + vt;
        const uint4 h = scp4[i4];
        scp4[i4] = base;
        gcp4[i4] = base;
        base = add4(base, h);
    }
    // g==7 threads now hold inclusive totals (packed) in `base`.

    // offsets: exclusive scan over v of totals, done by the g==7 warps
    unsigned t8 = 0, exl = 0;
    if (g == 7) {
        const unsigned s = base.x + base.y + base.z + base.w;
        t8 = (s & 0xffffu) + (s >> 16);      // total over this thread's 8 v's
        unsigned incl = t8;
        #pragma unroll
        for (int o = 1; o < 32; o <<= 1) {
            const unsigned n = __shfl_up_sync(0xffffffffu, incl, o);
            if (lane >= o) incl += n;
        }
        exl = incl - t8;
        if (lane == 31) wsum[vt >> 5] = incl;
    }
    __syncthreads();
    if (g == 7) {
        const int w = vt >> 5;
        unsigned run = exl;
        #pragma unroll
        for (int ww = 0; ww < 4; ww++)
            if (ww < w) run += wsum[ww];
        // unpack 8 totals, serial exclusive, pack offsets
        unsigned lanes[8];
        lanes[0] = base.x & 0xffffu; lanes[1] = base.x >> 16;
        lanes[2] = base.y & 0xffffu; lanes[3] = base.y >> 16;
        lanes[4] = base.z & 0xffffu; lanes[5] = base.z >> 16;
        lanes[6] = base.w & 0xffffu; lanes[7] = base.w >> 16;
        unsigned offs[8];
        #pragma unroll
        for (int k = 0; k < 8; k++) { offs[k] = run; run += lanes[k]; }
        const uint4 o4 = make_uint4(offs[0] | (offs[1] << 16),
                                    offs[2] | (offs[3] << 16),
                                    offs[4] | (offs[5] << 16),
                                    offs[6] | (offs[7] << 16));
        reinterpret_cast<uint4*>(soff)[vt] = o4;
        reinterpret_cast<uint4*>(&g_off[b][0])[vt] = o4;
    }
    __syncthreads();

    // CSR fill (sorted by construction), all reads from smem
    #pragma unroll
    for (int sg = warp; sg < NSEG; sg += 32) {
        const int s = sg * 32 + lane;
        const unsigned tok = srow[s];
        const unsigned mask = __match_any_sync(0xffffffffu, tok);
        const int rank = __popc(mask & ((1u << lane) - 1u));
        const int slot = (int)soff[tok] + (int)scp[sg * V + tok] + rank;
        g_occ[b][slot] = (unsigned short)s;
    }
}

// ---- K2: expand checkpoints to full per-position prefix rows ----
__global__ __launch_bounds__(256) void k_expand() {
    __shared__ unsigned short stok[32];
    const int seg = blockIdx.x, b = blockIdx.y;
    const int tid = threadIdx.x;
    if (tid < 32) stok[tid] = g_row[b][seg * 32 + tid];
    const int v0 = tid * 4;
    const uint2 cp = *reinterpret_cast<const uint2*>(&g_cp[b][seg][v0]);
    __syncthreads();

    unsigned a = cp.x, c = cp.y;            // packed (v0,v1), (v2,v3)
    #pragma unroll
    for (int s = 0; s < 32; s++) {
        const unsigned tok = stok[s];
        if (tok == (unsigned)(v0 + 0)) a += 1u;
        if (tok == (unsigned)(v0 + 1)) a += 0x10000u;
        if (tok == (unsigned)(v0 + 2)) c += 1u;
        if (tok == (unsigned)(v0 + 3)) c += 0x10000u;
        *reinterpret_cast<uint2*>(&g_pp[b][seg * 32 + s][v0]) =
            make_uint2(a, c);
    }
}

// ---- K3: main — one warp per t; 4 warps x TPW t's; no block barriers ----
__global__ __launch_bounds__(128, 8) void k4_main(const float* __restrict__ vw,
                                                  float* __restrict__ out) {
    __shared__ float acc[4][V];             // warp-private correction bins
    const int b = blockIdx.y;
    const int t_base = blockIdx.x * TPB;
    const int tid = threadIdx.x, lane = tid & 31, warp = tid >> 5;
    float* const wacc = acc[warp];
    const int voff = lane * 4;              // lane owns v = k*128 + voff + 0..3

    #pragma unroll
    for (int k = 0; k < 8; k++)
        *reinterpret_cast<float4*>(&wacc[k * 128 + voff]) =
            make_float4(0.f, 0.f, 0.f, 0.f);

    const float w0 = vw[0], w1 = vw[1], w2 = vw[2];
    const float L2E = 1.4426950408889634f;  // softmax in log2 domain
    const float w2s = w2 * L2E;
    const float a0s = (w0 - w2) * L2E, a1s = (w1 - w2) * L2E;
    const unsigned short* const rowb = g_row[b];
    const unsigned short* const offb = g_off[b];
    const unsigned short* const occb = g_occ[b];
    const unsigned short* const ppb  = &g_pp[b][0][0];
    __syncwarp();

    for (int i = 0; i < TPW; i++) {
        const int t = t_base + warp * TPW + i;
        const unsigned c = rowb[t];
        const int m = (int)g_pp[b][t][c];   // inclusive count of c at t (>=1)
        const int offc = offb[c];
        const bool fast = (m <= 31);        // m*C <= 31*2048 < 2^16
        const unsigned mu = fast ? (unsigned)m : 0u;
        const unsigned short* const rt = ppb + (size_t)t * V;

        // packed 2xu16 SIMD: pa = m*C(t) - sum_j C(q_j-1)  (borrow-free)
        unsigned pa[16];
        #pragma unroll
        for (int k = 0; k < 8; k++) {
            const uint2 w = *reinterpret_cast<const uint2*>(rt + k * 128 + voff);
            pa[2 * k]     = mu * w.x;
            pa[2 * k + 1] = mu * w.y;
        }

        for (int jb = 0; jb < m; jb += 32) {
            const int nj = min(32, m - jb);
            unsigned qv = 0;
            if (lane < nj) qv = occb[offc + jb + lane];
            for (int j = 0; j < nj; j++) {
                const int q = __shfl_sync(0xffffffffu, qv, j);
                if (fast) {
                    const unsigned short* rq =
                        (q > 0) ? ppb + (size_t)(q - 1) * V : g_zero;
                    #pragma unroll
                    for (int k = 0; k < 8; k++) {
                        const uint2 u =
                            *reinterpret_cast<const uint2*>(rq + k * 128 + voff);
                        pa[2 * k]     -= u.x;
                        pa[2 * k + 1] -= u.y;
                    }
                }
                if (q < t && lane == 0)     // bigram c -> next token
                    atomicAdd(&wacc[rowb[q + 1]], a1s);
            }
        }

        if (!fast) {  // exact cold path for m > 31 (i32, overflow-safe)
            #pragma unroll 1
            for (int k = 0; k < 8; k++) {
                const uint2 w =
                    *reinterpret_cast<const uint2*>(rt + k * 128 + voff);
                int l0 = m * (int)(w.x & 0xffffu);
                int l1 = m * (int)(w.x >> 16);
                int l2 = m * (int)(w.y & 0xffffu);
                int l3 = m * (int)(w.y >> 16);
                for (int j = 0; j < m; j++) {
                    const int q = occb[offc + j];
                    if (q > 0) {
                        const uint2 u = *reinterpret_cast<const uint2*>(
                            ppb + (size_t)(q - 1) * V + k * 128 + voff);
                        l0 -= (int)(u.x & 0xffffu); l1 -= (int)(u.x >> 16);
                        l2 -= (int)(u.y & 0xffffu); l3 -= (int)(u.y >> 16);
                    }
                }
                atomicAdd(&wacc[k * 128 + voff + 0], w2s * (float)l0);
                atomicAdd(&wacc[k * 128 + voff + 1], w2s * (float)l1);
                atomicAdd(&wacc[k * 128 + voff + 2], w2s * (float)l2);
                atomicAdd(&wacc[k * 128 + voff + 3], w2s * (float)l3);
            }
        }

        if (lane == 0) atomicAdd(&wacc[c], a0s * (float)m);   // a0 term
        __syncwarp();

        // assemble log2-scaled logits, warp-local softmax via EX2
        float a[32];
        float vmax = -3.0e38f;
        #pragma unroll
        for (int k = 0; k < 8; k++) {
            const float4 av =
                *reinterpret_cast<const float4*>(&wacc[k * 128 + voff]);
            *reinterpret_cast<float4*>(&wacc[k * 128 + voff]) =
                make_float4(0.f, 0.f, 0.f, 0.f);  // re-zero for next t
            a[4 * k + 0] = fmaf(w2s, (float)(pa[2 * k] & 0xffffu),     av.x);
            a[4 * k + 1] = fmaf(w2s, (float)(pa[2 * k] >> 16),         av.y);
            a[4 * k + 2] = fmaf(w2s, (float)(pa[2 * k + 1] & 0xffffu), av.z);
            a[4 * k + 3] = fmaf(w2s, (float)(pa[2 * k + 1] >> 16),     av.w);
            vmax = fmaxf(vmax, fmaxf(fmaxf(a[4 * k], a[4 * k + 1]),
                                     fmaxf(a[4 * k + 2], a[4 * k + 3])));
        }
        #pragma unroll
        for (int o = 16; o; o >>= 1)
            vmax = fmaxf(vmax, __shfl_xor_sync(0xffffffffu, vmax, o));

        float ssum = 0.f;
        #pragma unroll
        for (int k = 0; k < 32; k++) {
            a[k] = ex2(a[k] - vmax);
            ssum += a[k];
        }
        #pragma unroll
        for (int o = 16; o; o >>= 1)
            ssum += __shfl_xor_sync(0xffffffffu, ssum, o);
        const float inv = 1.0f / ssum;

        float* const orow = out + (size_t)(b * T + t) * V + voff;
        #pragma unroll
        for (int k = 0; k < 8; k++)
            *reinterpret_cast<float4*>(orow + k * 128) =
                make_float4(a[4 * k] * inv, a[4 * k + 1] * inv,
                            a[4 * k + 2] * inv, a[4 * k + 3] * inv);

        __syncwarp();   // acc re-zero visible before next t's atomics
    }
}

extern "C" void kernel_launch(void* const* d_in, const int* in_sizes, int n_in,
                              void* d_out, int out_size) {
    const int*   idx = (const int*)d_in[0];
    const float* vw  = (const float*)d_in[1];
    float*       out = (float*)d_out;
    (void)in_sizes; (void)n_in; (void)out_size;

    static bool attr_done = false;
    if (!attr_done) {
        cudaFuncSetAttribute(k_setup,
                             cudaFuncAttributeMaxDynamicSharedMemorySize,
                             SETUP_SMEM);
        attr_done = true;
    }

    k_setup <<<dim3(B), 1024, SETUP_SMEM>>>(idx);
    k_expand<<<dim3(NSEG, B), 256>>>();
    k4_main <<<dim3(T / TPB, B), 128>>>(vw, out);
}

// round 13
// speedup vs baseline: 1.5150x; 1.0934x over previous
#include <cuda_runtime.h>

// B=8, T=2048, V=1024.
// c = idx[b,t]; q_1..q_m = occurrences of c in [0..t]; C_v(r) = inclusive
// prefix histogram:
//   L_t[v] = w2*( m*C_v(t) - sum_j C_v(q_j-1) ) + a0*m*[v==c]
//            + a1*#{j : q_j+1 <= t, idx(q_j+1)==v},   out = softmax(L_t).
// k_se (grid 8xB, 150KB smem): per-block full segment-hist table -> packed
// uint4 bases -> writes INCLUSIVE per-position prefix rows g_pp directly
// (expand fused) + CSR offsets/occurrence lists. k4_main: one warp per t,
// packed 2xu16 SIMD gather over g_pp rows, softmax via ex2 in log2 domain.

namespace {
constexpr int B = 8, T = 2048, V = 1024;
constexpr int NSEG = 64;                    // T/32 segments
constexpr int TPW = 2;                      // t's per warp
constexpr int TPB = 4 * TPW;                // t's per block
constexpr int SE_SMEM =
    NSEG * V * 2      // shist [64][1024] u16
    + T * 2           // srow  [2048] u16
    + V * 2           // soff  [1024] u16
    + 8 * V * 2       // spart [8][1024] u16
    + 16;             // wsum  [4] u32
}

__device__ __align__(16) unsigned short g_pp[B][T][V];     // incl. full prefix
__device__ __align__(16) unsigned short g_row[B][T];
__device__ __align__(16) unsigned short g_off[B][V];       // CSR offsets
__device__ __align__(16) unsigned short g_occ[B][T];       // CSR positions
__device__ __align__(16) unsigned short g_zero[V];         // stays all-zero

__device__ __forceinline__ float ex2(float x) {
    float y;
    asm("ex2.approx.ftz.f32 %0, %1;" : "=f"(y) : "f"(x));
    return y;
}
__device__ __forceinline__ uint4 add4(uint4 a, uint4 b) {
    return make_uint4(a.x + b.x, a.y + b.y, a.z + b.z, a.w + b.w);
}

// ---- K1: setup + expand fused; block (g,b) owns segments 8g..8g+7 ----
__global__ __launch_bounds__(1024) void k_se(const int* __restrict__ idx) {
    extern __shared__ __align__(16) unsigned char smem_raw[];
    unsigned short* const shist = (unsigned short*)smem_raw;     // [64][1024]
    unsigned short* const srow  = shist + NSEG * V;              // [2048]
    unsigned short* const soff  = srow + T;                      // [1024]
    unsigned short* const spart = soff + V;                      // [8][1024]
    unsigned* const wsum = (unsigned*)(spart + 8 * V);           // [4]
    uint4* const shist4 = (uint4*)shist;
    uint4* const spart4 = (uint4*)spart;

    const int g = blockIdx.x, b = blockIdx.y;
    const int tid = threadIdx.x, lane = tid & 31, warp = tid >> 5;
    const int team = tid >> 7, vt = tid & 127;   // team 0..7, uint4 lane 0..127
    const int seg = g * 8 + team;                // this team's segment

    // row load (+ single mirror to global by g==0 blocks)
    const int2 tt = reinterpret_cast<const int2*>(idx + b * T)[tid];
    srow[2 * tid]     = (unsigned short)tt.x;
    srow[2 * tid + 1] = (unsigned short)tt.y;
    if (g == 0)
        reinterpret_cast<ushort2*>(g_row[b])[tid] =
            make_ushort2((unsigned short)tt.x, (unsigned short)tt.y);

    // zero hist table
    const uint4 z = make_uint4(0, 0, 0, 0);
    #pragma unroll
    for (int k = 0; k < 8; k++)
        shist4[k * 1024 + tid] = z;
    __syncthreads();

    // per-segment counts via match_any (warp w: segments w and w+32)
    #pragma unroll
    for (int sg = warp; sg < NSEG; sg += 32) {
        const unsigned tok = srow[sg * 32 + lane];
        const unsigned mask = __match_any_sync(0xffffffffu, tok);
        if ((mask & ((1u << lane) - 1u)) == 0u)
            shist[sg * V + tok] = (unsigned short)__popc(mask);
    }
    __syncthreads();

    // team partials: spart[team] = sum of this team's 8 segment hists (packed)
    uint4 ps = z;
    #pragma unroll
    for (int k = 0; k < 8; k++)
        ps = add4(ps, shist4[(team * 8 + k) * 128 + vt]);
    spart4[team * 128 + vt] = ps;
    __syncthreads();

    // CSR offsets (team 0 computes the exclusive scan over v of totals)
    uint4 tot = z;
    unsigned exl = 0;
    if (team == 0) {
        #pragma unroll
        for (int tau = 0; tau < 8; tau++)
            tot = add4(tot, spart4[tau * 128 + vt]);
        const unsigned s = tot.x + tot.y + tot.z + tot.w;
        const unsigned t8 = (s & 0xffffu) + (s >> 16);
        unsigned incl = t8;
        #pragma unroll
        for (int o = 1; o < 32; o <<= 1) {
            const unsigned n = __shfl_up_sync(0xffffffffu, incl, o);
            if (lane >= o) incl += n;
        }
        exl = incl - t8;
        if (lane == 31) wsum[warp] = incl;
    }
    __syncthreads();
    if (team == 0) {
        unsigned run = exl;
        #pragma unroll
        for (int ww = 0; ww < 4; ww++)
            if (ww < warp) run += wsum[ww];
        unsigned lanes[8];
        lanes[0] = tot.x & 0xffffu; lanes[1] = tot.x >> 16;
        lanes[2] = tot.y & 0xffffu; lanes[3] = tot.y >> 16;
        lanes[4] = tot.z & 0xffffu; lanes[5] = tot.z >> 16;
        lanes[6] = tot.w & 0xffffu; lanes[7] = tot.w >> 16;
        unsigned offs[8];
        #pragma unroll
        for (int k = 0; k < 8; k++) { offs[k] = run; run += lanes[k]; }
        const uint4 o4 = make_uint4(offs[0] | (offs[1] << 16),
                                    offs[2] | (offs[3] << 16),
                                    offs[4] | (offs[5] << 16),
                                    offs[6] | (offs[7] << 16));
        reinterpret_cast<uint4*>(soff)[vt] = o4;
        if (g == 0)
            reinterpret_cast<uint4*>(&g_off[b][0])[vt] = o4;
    }

    // exclusive base at the start of this team's segment (packed)
    uint4 base = z;
    for (int G = 0; G < g; G++)
        base = add4(base, spart4[G * 128 + vt]);
    for (int k = 0; k < team; k++)
        base = add4(base, shist4[(g * 8 + k) * 128 + vt]);
    __syncthreads();                 // all base reads done before overwrite

    // publish exclusive segment-start counts (for CSR fill) into shist[seg]
    shist4[seg * 128 + vt] = base;
    __syncthreads();

    // CSR fill for this segment (first warp of each team)
    if ((tid & 127) < 32) {
        const int s = seg * 32 + lane;
        const unsigned tok = srow[s];
        const unsigned mask = __match_any_sync(0xffffffffu, tok);
        const int rank = __popc(mask & ((1u << lane) - 1u));
        const int slot = (int)soff[tok] + (int)shist[seg * V + tok] + rank;
        g_occ[b][slot] = (unsigned short)s;
    }

    // expand: walk 32 positions, write INCLUSIVE prefix rows to g_pp
    #pragma unroll
    for (int s = 0; s < 32; s++) {
        const unsigned tok = srow[seg * 32 + s];
        const unsigned u = tok - 8u * (unsigned)vt;   // wraps if below range
        if (u < 8u) {
            const unsigned inc = 1u << ((u & 1u) << 4);
            const unsigned cj = u >> 1;
            if (cj == 0) base.x += inc;
            else if (cj == 1) base.y += inc;
            else if (cj == 2) base.z += inc;
            else base.w += inc;
        }
        *reinterpret_cast<uint4*>(&g_pp[b][seg * 32 + s][vt * 8]) = base;
    }
}

// ---- K2: main — one warp per t; 4 warps x TPW t's; no block barriers ----
__global__ __launch_bounds__(128, 8) void k4_main(const float* __restrict__ vw,
                                                  float* __restrict__ out) {
    __shared__ float acc[4][V];             // warp-private correction bins
    const int b = blockIdx.y;
    const int t_base = blockIdx.x * TPB;
    const int tid = threadIdx.x, lane = tid & 31, warp = tid >> 5;
    float* const wacc = acc[warp];
    const int voff = lane * 4;              // lane owns v = k*128 + voff + 0..3

    #pragma unroll
    for (int k = 0; k < 8; k++)
        *reinterpret_cast<float4*>(&wacc[k * 128 + voff]) =
            make_float4(0.f, 0.f, 0.f, 0.f);

    const float w0 = vw[0], w1 = vw[1], w2 = vw[2];
    const float L2E = 1.4426950408889634f;  // softmax in log2 domain
    const float w2s = w2 * L2E;
    const float a0s = (w0 - w2) * L2E, a1s = (w1 - w2) * L2E;
    const unsigned short* const rowb = g_row[b];
    const unsigned short* const offb = g_off[b];
    const unsigned short* const occb = g_occ[b];
    const unsigned short* const ppb  = &g_pp[b][0][0];
    __syncwarp();

    for (int i = 0; i < TPW; i++) {
        const int t = t_base + warp * TPW + i;
        const unsigned c = rowb[t];
        const int m = (int)g_pp[b][t][c];   // inclusive count of c at t (>=1)
        const int offc = offb[c];
        const bool fast = (m <= 31);        // m*C <= 31*2048 < 2^16
        const unsigned mu = fast ? (unsigned)m : 0u;
        const unsigned short* const rt = ppb + (size_t)t * V;

        // packed 2xu16 SIMD: pa = m*C(t) - sum_j C(q_j-1)  (borrow-free)
        unsigned pa[16];
        #pragma unroll
        for (int k = 0; k < 8; k++) {
            const uint2 w = *reinterpret_cast<const uint2*>(rt + k * 128 + voff);
            pa[2 * k]     = mu * w.x;
            pa[2 * k + 1] = mu * w.y;
        }

        for (int jb = 0; jb < m; jb += 32) {
            const int nj = min(32, m - jb);
            unsigned qv = 0;
            if (lane < nj) qv = occb[offc + jb + lane];
            for (int j = 0; j < nj; j++) {
                const int q = __shfl_sync(0xffffffffu, qv, j);
                if (fast) {
                    const unsigned short* rq =
                        (q > 0) ? ppb + (size_t)(q - 1) * V : g_zero;
                    #pragma unroll
                    for (int k = 0; k < 8; k++) {
                        const uint2 u =
                            *reinterpret_cast<const uint2*>(rq + k * 128 + voff);
                        pa[2 * k]     -= u.x;
                        pa[2 * k + 1] -= u.y;
                    }
                }
                if (q < t && lane == 0)     // bigram c -> next token
                    atomicAdd(&wacc[rowb[q + 1]], a1s);
            }
        }

        if (!fast) {  // exact cold path for m > 31 (i32, overflow-safe)
            #pragma unroll 1
            for (int k = 0; k < 8; k++) {
                const uint2 w =
                    *reinterpret_cast<const uint2*>(rt + k * 128 + voff);
                int l0 = m * (int)(w.x & 0xffffu);
                int l1 = m * (int)(w.x >> 16);
                int l2 = m * (int)(w.y & 0xffffu);
                int l3 = m * (int)(w.y >> 16);
                for (int j = 0; j < m; j++) {
                    const int q = occb[offc + j];
                    if (q > 0) {
                        const uint2 u = *reinterpret_cast<const uint2*>(
                            ppb + (size_t)(q - 1) * V + k * 128 + voff);
                        l0 -= (int)(u.x & 0xffffu); l1 -= (int)(u.x >> 16);
                        l2 -= (int)(u.y & 0xffffu); l3 -= (int)(u.y >> 16);
                    }
                }
                atomicAdd(&wacc[k * 128 + voff + 0], w2s * (float)l0);
                atomicAdd(&wacc[k * 128 + voff + 1], w2s * (float)l1);
                atomicAdd(&wacc[k * 128 + voff + 2], w2s * (float)l2);
                atomicAdd(&wacc[k * 128 + voff + 3], w2s * (float)l3);
            }
        }

        if (lane == 0) atomicAdd(&wacc[c], a0s * (float)m);   // a0 term
        __syncwarp();

        // assemble log2-scaled logits, warp-local softmax via EX2
        float a[32];
        float vmax = -3.0e38f;
        #pragma unroll
        for (int k = 0; k < 8; k++) {
            const float4 av =
                *reinterpret_cast<const float4*>(&wacc[k * 128 + voff]);
            *reinterpret_cast<float4*>(&wacc[k * 128 + voff]) =
                make_float4(0.f, 0.f, 0.f, 0.f);  // re-zero for next t
            a[4 * k + 0] = fmaf(w2s, (float)(pa[2 * k] & 0xffffu),     av.x);
            a[4 * k + 1] = fmaf(w2s, (float)(pa[2 * k] >> 16),         av.y);
            a[4 * k + 2] = fmaf(w2s, (float)(pa[2 * k + 1] & 0xffffu), av.z);
            a[4 * k + 3] = fmaf(w2s, (float)(pa[2 * k + 1] >> 16),     av.w);
            vmax = fmaxf(vmax, fmaxf(fmaxf(a[4 * k], a[4 * k + 1]),
                                     fmaxf(a[4 * k + 2], a[4 * k + 3])));
        }
        #pragma unroll
        for (int o = 16; o; o >>= 1)
            vmax = fmaxf(vmax, __shfl_xor_sync(0xffffffffu, vmax, o));

        float ssum = 0.f;
        #pragma unroll
        for (int k = 0; k < 32; k++) {
            a[k] = ex2(a[k] - vmax);
            ssum += a[k];
        }
        #pragma unroll
        for (int o = 16; o; o >>= 1)
            ssum += __shfl_xor_sync(0xffffffffu, ssum, o);
        const float inv = 1.0f / ssum;

        float* const orow = out + (size_t)(b * T + t) * V + voff;
        #pragma unroll
        for (int k = 0; k < 8; k++)
            *reinterpret_cast<float4*>(orow + k * 128) =
                make_float4(a[4 * k] * inv, a[4 * k + 1] * inv,
                            a[4 * k + 2] * inv, a[4 * k + 3] * inv);

        __syncwarp();   // acc re-zero visible before next t's atomics
    }
}

extern "C" void kernel_launch(void* const* d_in, const int* in_sizes, int n_in,
                              void* d_out, int out_size) {
    const int*   idx = (const int*)d_in[0];
    const float* vw  = (const float*)d_in[1];
    float*       out = (float*)d_out;
    (void)in_sizes; (void)n_in; (void)out_size;

    static bool attr_done = false;
    if (!attr_done) {
        cudaFuncSetAttribute(k_se,
                             cudaFuncAttributeMaxDynamicSharedMemorySize,
                             SE_SMEM);
        attr_done = true;
    }

    k_se   <<<dim3(8, B), 1024, SE_SMEM>>>(idx);
    k4_main<<<dim3(T / TPB, B), 128>>>(vw, out);
}